// round 15
// baseline (speedup 1.0000x reference)
#include <cuda_runtime.h>
#include <cuda_fp16.h>
#include <cstdint>
#include <math.h>

// ---------------------------------------------------------------------------
// Problem constants
// ---------------------------------------------------------------------------
#define NTOK      49
#define DIM       384
#define NHEADS    12
#define HD        32
#define NWIN      4096
#define NMASK     1024
#define M_TOTAL   (NWIN * NTOK)     // 200704
#define QKV_N     (3 * DIM)         // 1152
#define KTOT      384
#define ATTN_SCALE 0.17677669529663687f
#define BM_STR    2404              // padded bias+mask row (floats, 16B-aligned)

// Scratch (__device__ globals; allocation-free rule)
__device__ __align__(128) __half g_qkvh[(size_t)M_TOTAL * QKV_N];
__device__ __align__(128) __half g_xh [(size_t)M_TOTAL * DIM];
__device__ __align__(128) __half g_ah [(size_t)M_TOTAL * DIM];
__device__ __align__(128) __half g_wqh[QKV_N * DIM];
__device__ __align__(128) __half g_wph[DIM * DIM];
__device__ __align__(128) float  g_bias12[NHEADS * BM_STR];              // gathered rpb
__device__ __align__(128) float  g_bm[(size_t)NMASK * NHEADS * BM_STR];  // bias+mask fused

// ---------------------------------------------------------------------------
// Helpers
// ---------------------------------------------------------------------------
__device__ __forceinline__ uint32_t smem_u32(const void* p) {
    uint32_t a;
    asm("{ .reg .u64 t; cvta.to.shared.u64 t, %1; cvt.u32.u64 %0, t; }" : "=r"(a) : "l"(p));
    return a;
}

__device__ __forceinline__ void cpa16(uint32_t dst, const void* src) {
    asm volatile("cp.async.cg.shared.global [%0], [%1], 16;" :: "r"(dst), "l"(src) : "memory");
}
#define CP_COMMIT() asm volatile("cp.async.commit_group;" ::: "memory")
#define CP_WAIT1()  asm volatile("cp.async.wait_group 1;" ::: "memory")
#define CP_WAIT0()  asm volatile("cp.async.wait_group 0;" ::: "memory")

__device__ __forceinline__ void mma_f16(float* d, const uint32_t* a, const uint32_t* b) {
    asm volatile(
        "mma.sync.aligned.m16n8k16.row.col.f32.f16.f16.f32 "
        "{%0,%1,%2,%3}, {%4,%5,%6,%7}, {%8,%9}, {%0,%1,%2,%3};"
        : "+f"(d[0]), "+f"(d[1]), "+f"(d[2]), "+f"(d[3])
        : "r"(a[0]), "r"(a[1]), "r"(a[2]), "r"(a[3]), "r"(b[0]), "r"(b[1]));
}

__device__ __forceinline__ void ldsm_x4(uint32_t* r, uint32_t addr) {
    asm volatile("ldmatrix.sync.aligned.m8n8.x4.shared.b16 {%0,%1,%2,%3}, [%4];"
                 : "=r"(r[0]), "=r"(r[1]), "=r"(r[2]), "=r"(r[3]) : "r"(addr));
}
__device__ __forceinline__ void ldsm_x4_t(uint32_t* r, uint32_t addr) {
    asm volatile("ldmatrix.sync.aligned.m8n8.x4.trans.shared.b16 {%0,%1,%2,%3}, [%4];"
                 : "=r"(r[0]), "=r"(r[1]), "=r"(r[2]), "=r"(r[3]) : "r"(addr));
}

// ---------------------------------------------------------------------------
// fp16 tensor-core GEMM (exact round-12 proven version: BK=32, 3 stages)
// ---------------------------------------------------------------------------
#define BKH      32
#define NSTAGE   3
#define KITERS   (KTOT / BKH)
#define SROWW    20
#define STAGEW   (128 * SROWW)
#define SMEM_TOT (NSTAGE * STAGEW * 2 * 4)

template <typename OutT>
__global__ __launch_bounds__(256, 2)
void gemm_mma_kernel(const __half* __restrict__ A,
                     const __half* __restrict__ W,
                     const float* __restrict__ bias,
                     OutT* __restrict__ C,
                     int Ntot) {
    extern __shared__ __align__(16) uint32_t sm[];
    uint32_t* Asm = sm;
    uint32_t* Bsm = sm + NSTAGE * STAGEW;

    const int tid  = threadIdx.x;
    const int warp = tid >> 5;
    const int lane = tid & 31;
    const int gid  = lane >> 2;
    const int tig  = lane & 3;
    const int wm   = warp & 1;
    const int wn   = warp >> 1;
    const int mb   = blockIdx.y * 128;
    const int nb   = blockIdx.x * 128;

    const int aLane = ((lane & 7) + 8 * ((lane >> 3) & 1)) * SROWW + 4 * (lane >> 4);
    const int bLane = ((lane & 7) + 8 * (lane >> 4)) * SROWW + 4 * ((lane >> 3) & 1);

    auto load_stage = [&](int s, int kt) {
        uint32_t* as = Asm + s * STAGEW;
        uint32_t* bs = Bsm + s * STAGEW;
        const int k0 = kt * BKH;
        #pragma unroll
        for (int i = 0; i < 2; i++) {
            const int f = tid + i * 256;
            const int m = f >> 2;
            const int g = f & 3;
            cpa16(smem_u32(as + m * SROWW + g * 4), A + (size_t)(mb + m) * KTOT + k0 + g * 8);
            cpa16(smem_u32(bs + m * SROWW + g * 4), W + (size_t)(nb + m) * KTOT + k0 + g * 8);
        }
    };

    float acc[4][4][4];
    #pragma unroll
    for (int mt = 0; mt < 4; mt++)
        #pragma unroll
        for (int nt = 0; nt < 4; nt++)
            #pragma unroll
            for (int r = 0; r < 4; r++) acc[mt][nt][r] = 0.0f;

    load_stage(0, 0); CP_COMMIT();
    load_stage(1, 1); CP_COMMIT();

    for (int kt = 0; kt < KITERS; ++kt) {
        CP_WAIT1();
        __syncthreads();

        const int s = kt % NSTAGE;
        if (kt + 2 < KITERS) load_stage((kt + 2) % NSTAGE, kt + 2);
        CP_COMMIT();

        const uint32_t aS = smem_u32(Asm + s * STAGEW);
        const uint32_t bS = smem_u32(Bsm + s * STAGEW);

        #pragma unroll
        for (int ks = 0; ks < 2; ks++) {
            const int kw = ks * 8;
            uint32_t af[4][4], bf[4][2];
            #pragma unroll
            for (int mt = 0; mt < 4; mt++) {
                const int base = (wm * 64 + mt * 16) * SROWW + kw + aLane;
                ldsm_x4(af[mt], aS + base * 4);
            }
            #pragma unroll
            for (int np = 0; np < 2; np++) {
                uint32_t q[4];
                const int base = (wn * 32 + np * 16) * SROWW + kw + bLane;
                ldsm_x4(q, bS + base * 4);
                bf[2 * np + 0][0] = q[0]; bf[2 * np + 0][1] = q[1];
                bf[2 * np + 1][0] = q[2]; bf[2 * np + 1][1] = q[3];
            }
            #pragma unroll
            for (int mt = 0; mt < 4; mt++)
                #pragma unroll
                for (int nt = 0; nt < 4; nt++)
                    mma_f16(acc[mt][nt], af[mt], bf[nt]);
        }
    }

    #pragma unroll
    for (int mt = 0; mt < 4; mt++) {
        const int row = mb + wm * 64 + mt * 16 + gid;
        #pragma unroll
        for (int nt = 0; nt < 4; nt++) {
            const int col = nb + wn * 32 + nt * 8 + 2 * tig;
            const float b0 = bias[col], b1 = bias[col + 1];
            if constexpr (sizeof(OutT) == 4) {
                float2 v0 = make_float2(acc[mt][nt][0] + b0, acc[mt][nt][1] + b1);
                float2 v1 = make_float2(acc[mt][nt][2] + b0, acc[mt][nt][3] + b1);
                *reinterpret_cast<float2*>((float*)C + (size_t)row * Ntot + col)       = v0;
                *reinterpret_cast<float2*>((float*)C + (size_t)(row + 8) * Ntot + col) = v1;
            } else {
                __half2 h0 = __floats2half2_rn(acc[mt][nt][0] + b0, acc[mt][nt][1] + b1);
                __half2 h1 = __floats2half2_rn(acc[mt][nt][2] + b0, acc[mt][nt][3] + b1);
                *reinterpret_cast<__half2*>((__half*)C + (size_t)row * Ntot + col)       = h0;
                *reinterpret_cast<__half2*>((__half*)C + (size_t)(row + 8) * Ntot + col) = h1;
            }
        }
    }
}

// ---------------------------------------------------------------------------
// Prep kernels (proven round-12 versions)
// ---------------------------------------------------------------------------
__global__ void f2h_kernel(const float4* __restrict__ in,
                           uint2* __restrict__ out, int n4) {
    int i = blockIdx.x * blockDim.x + threadIdx.x;
    if (i < n4) {
        float4 v = in[i];
        __half2 h0 = __floats2half2_rn(v.x, v.y);
        __half2 h1 = __floats2half2_rn(v.z, v.w);
        uint2 u;
        u.x = *reinterpret_cast<uint32_t*>(&h0);
        u.y = *reinterpret_cast<uint32_t*>(&h1);
        out[i] = u;
    }
}

__global__ void bias12_prep_kernel(const float* __restrict__ rpb,
                                   const int* __restrict__ rel_idx,
                                   float* __restrict__ out) {
    int i = blockIdx.x * blockDim.x + threadIdx.x;
    if (i < NHEADS * BM_STR) {
        const int h = i / BM_STR;
        const int e = i - h * BM_STR;
        out[i] = (e < NTOK * NTOK) ? rpb[rel_idx[e] * NHEADS + h] : 0.0f;
    }
}

__global__ void bm_stream_kernel(const float* __restrict__ bias12,
                                 const float* __restrict__ mask,
                                 float* __restrict__ out) {
    const int row = blockIdx.x;
    const int m = row / NHEADS;
    const int h = row - m * NHEADS;
    const float* mrow = mask + (size_t)m * (NTOK * NTOK);
    const float4* brow = reinterpret_cast<const float4*>(bias12 + h * BM_STR);
    float4* orow = reinterpret_cast<float4*>(out + (size_t)row * BM_STR);
    for (int g = threadIdx.x; g < BM_STR / 4; g += 256) {
        const int e0 = g * 4;
        float4 b = brow[g];
        float4 v;
        v.x = (e0 + 0 < NTOK * NTOK) ? b.x + mrow[e0 + 0] : 0.0f;
        v.y = (e0 + 1 < NTOK * NTOK) ? b.y + mrow[e0 + 1] : 0.0f;
        v.z = (e0 + 2 < NTOK * NTOK) ? b.z + mrow[e0 + 2] : 0.0f;
        v.w = (e0 + 3 < NTOK * NTOK) ? b.w + mrow[e0 + 3] : 0.0f;
        orow[g] = v;
    }
}

// ---------------------------------------------------------------------------
// Window attention: PAIRED windows. 256 threads; warps 0-3 handle window
// m + a*2048, warps 4-7 handle m+1024 + a*2048. Both share the bm row
// (loaded once). Per-half code identical to the proven round-8/12 kernel.
// ---------------------------------------------------------------------------
__global__ __launch_bounds__(256, 3)
void win_attn_kernel(const __half* __restrict__ qkv,
                     const float* __restrict__ bm,
                     __half* __restrict__ attout) {
    const int h    = blockIdx.x % NHEADS;
    const int pair = blockIdx.x / NHEADS;          // 0..2047
    const int m    = pair & (NMASK - 1);
    const int a    = pair >> 10;                   // 0 or 1
    const int tid  = threadIdx.x;
    const int sub  = tid >> 7;                     // which window half
    const int wtid = tid & 127;
    const int w    = m + a * 2048 + sub * 1024;

    const int warp = wtid >> 5;
    const int lane = wtid & 31;
    const int gid  = lane >> 2;
    const int tig  = lane & 3;

    __shared__ __align__(16) char  ub[2][64 * 40 * 2 * 2];   // Q+K per half; P aliases
    __shared__ __align__(16) __half Vh[2][64][40];
    __shared__ __align__(16) float  Sf[2][NTOK][57];
    __shared__ __align__(16) float  BMs[BM_STR];             // shared by both halves

    __half (*Qh)[40] = reinterpret_cast<__half(*)[40]>(ub[sub]);
    __half (*Kh)[40] = reinterpret_cast<__half(*)[40]>(ub[sub] + 64 * 40 * 2);
    __half (*Ph)[72] = reinterpret_cast<__half(*)[72]>(ub[sub]);
    float  (*Sfp)[57] = Sf[sub];

    // ---- Prefetch: per-half qkv rows; bm row once by all 256 threads ----
    const __half* base = qkv + (size_t)w * NTOK * QKV_N + h * HD;
    for (int idx = wtid; idx < 3 * NTOK * 4; idx += 128) {
        const int mm = idx / (NTOK * 4);
        const int rem = idx - mm * (NTOK * 4);
        const int i = rem >> 2;
        const int g = rem & 3;
        __half* dst = (mm == 0) ? &Qh[i][0] : (mm == 1) ? &Kh[i][0] : &Vh[sub][i][0];
        cpa16(smem_u32(dst + g * 8), base + (size_t)i * QKV_N + mm * DIM + g * 8);
    }
    {
        const float* bmrow = bm + (size_t)(m * NHEADS + h) * BM_STR;
        for (int idx = tid; idx < BM_STR / 4; idx += 256)
            cpa16(smem_u32(&BMs[idx * 4]), bmrow + idx * 4);
    }
    CP_COMMIT();

    // ---- Zero pad rows 49..63 of Q/K/V while loads are in flight ----
    const uint4 z4 = make_uint4(0, 0, 0, 0);
    for (int idx = wtid; idx < 225; idx += 128) {
        const int aa = idx / 75;
        const int rem = idx - aa * 75;
        const int r = 49 + rem / 5;
        const int g = rem % 5;
        __half* dst = (aa == 0) ? &Qh[r][0] : (aa == 1) ? &Kh[r][0] : &Vh[sub][r][0];
        reinterpret_cast<uint4*>(dst)[g] = z4;
    }
    CP_WAIT0();
    __syncthreads();

    // ---- Scores: S = Q K^T ----
    const uint32_t QS = smem_u32(&Qh[0][0]);
    const uint32_t KS = smem_u32(&Kh[0][0]);
    const int aL = ((lane & 7) + 8 * ((lane >> 3) & 1)) * 20 + 4 * (lane >> 4);
    const int bL = ((lane & 7) + 8 * (lane >> 4)) * 20 + 4 * ((lane >> 3) & 1);

    float acc[8][4];
    #pragma unroll
    for (int q = 0; q < 8; q++)
        #pragma unroll
        for (int r = 0; r < 4; r++) acc[q][r] = 0.0f;

    #pragma unroll
    for (int ks = 0; ks < 2; ks++) {
        uint32_t af[4];
        ldsm_x4(af, QS + (uint32_t)(warp * 16 * 20 + ks * 8 + aL) * 4);
        #pragma unroll
        for (int nb = 0; nb < 4; nb++) {
            uint32_t q[4];
            ldsm_x4(q, KS + (uint32_t)(nb * 16 * 20 + ks * 8 + bL) * 4);
            mma_f16(acc[nb * 2 + 0], af, q + 0);
            mma_f16(acc[nb * 2 + 1], af, q + 2);
        }
    }

    // scores + scale + fused bias/mask from smem (shared BMs)
    {
        const int i0 = warp * 16 + gid;
        #pragma unroll
        for (int nt = 0; nt < 8; nt++) {
            const int j = nt * 8 + 2 * tig;
            if (j < NTOK) {
                #pragma unroll
                for (int rr = 0; rr < 2; rr++) {
                    const int i = i0 + rr * 8;
                    if (i < NTOK) {
                        const int e = i * NTOK + j;
                        Sfp[i][j] = fmaf(acc[nt][rr * 2], ATTN_SCALE, BMs[e]);
                        if (j + 1 < NTOK)
                            Sfp[i][j + 1] = fmaf(acc[nt][rr * 2 + 1], ATTN_SCALE, BMs[e + 1]);
                    }
                }
            }
        }
    }
    __syncthreads();   // Sf complete; Q/K dead -> Ph region reusable

    // ---- Softmax rows (wtid 0..48) || P pad-zeroing (wtid 49..127) ----
    if (wtid < NTOK) {
        const int i = wtid;
        float mx = -1e30f;
        #pragma unroll 7
        for (int j = 0; j < NTOK; j++) mx = fmaxf(mx, Sfp[i][j]);
        float s = 0.0f;
        #pragma unroll 7
        for (int j = 0; j < NTOK; j++) {
            const float e = __expf(Sfp[i][j] - mx);
            Sfp[i][j] = e;
            s += e;
        }
        const float inv = 1.0f / s;
        #pragma unroll 7
        for (int j = 0; j < NTOK; j++)
            Ph[i][j] = __float2half_rn(Sfp[i][j] * inv);
        #pragma unroll
        for (int j = NTOK; j < 56; j++)
            Ph[i][j] = __ushort_as_half((unsigned short)0);
    } else {
        for (int idx = wtid - NTOK; idx < 233; idx += 128 - NTOK) {
            int r, c;
            if (idx < 135) { r = 49 + idx / 9; c = (idx % 9) * 8; }
            else           { const int q = idx - 135; r = q >> 1; c = 56 + (q & 1) * 8; }
            *reinterpret_cast<uint4*>(&Ph[r][c]) = z4;
        }
    }
    __syncthreads();

    // ---- PV: O = P V ----
    const uint32_t PS = smem_u32(&Ph[0][0]);
    const uint32_t VS = smem_u32(&Vh[sub][0][0]);
    const int aLp = ((lane & 7) + 8 * ((lane >> 3) & 1)) * 36 + 4 * (lane >> 4);
    const int vL  = ((lane & 7) + 8 * ((lane >> 3) & 1)) * 20 + 4 * (lane >> 4);

    float pacc[4][4];
    #pragma unroll
    for (int q = 0; q < 4; q++)
        #pragma unroll
        for (int r = 0; r < 4; r++) pacc[q][r] = 0.0f;

    #pragma unroll
    for (int ks = 0; ks < 4; ks++) {
        uint32_t pf[4];
        ldsm_x4(pf, PS + (uint32_t)(warp * 16 * 36 + ks * 8 + aLp) * 4);
        uint32_t v0[4], v1[4];
        ldsm_x4_t(v0, VS + (uint32_t)(ks * 16 * 20 + vL) * 4);
        ldsm_x4_t(v1, VS + (uint32_t)(ks * 16 * 20 + 8 + vL) * 4);
        mma_f16(pacc[0], pf, v0 + 0);
        mma_f16(pacc[1], pf, v0 + 2);
        mma_f16(pacc[2], pf, v1 + 0);
        mma_f16(pacc[3], pf, v1 + 2);
    }

    // ---- Store O (fp16) ----
    {
        __half* ob = attout + (size_t)w * NTOK * DIM + h * HD;
        const int i0 = warp * 16 + gid;
        #pragma unroll
        for (int nt = 0; nt < 4; nt++) {
            const int d = nt * 8 + 2 * tig;
            #pragma unroll
            for (int rr = 0; rr < 2; rr++) {
                const int i = i0 + rr * 8;
                if (i < NTOK) {
                    __half2 hv = __floats2half2_rn(pacc[nt][rr * 2], pacc[nt][rr * 2 + 1]);
                    *reinterpret_cast<__half2*>(ob + (size_t)i * DIM + d) = hv;
                }
            }
        }
    }
}

// ---------------------------------------------------------------------------
// Launch
// ---------------------------------------------------------------------------
extern "C" void kernel_launch(void* const* d_in, const int* in_sizes, int n_in,
                              void* d_out, int out_size) {
    const float* x      = (const float*)d_in[0];
    const float* mask   = (const float*)d_in[1];
    const float* rpb    = (const float*)d_in[2];
    const float* qkv_w  = (const float*)d_in[3];
    const float* qkv_b  = (const float*)d_in[4];
    const float* proj_w = (const float*)d_in[5];
    const float* proj_b = (const float*)d_in[6];
    const int*   rel_i  = (const int*)d_in[7];
    float* out = (float*)d_out;

    __half *qkvh, *xh, *ah, *wqh, *wph;
    float *bmb, *biasb;
    cudaGetSymbolAddress((void**)&qkvh, g_qkvh);
    cudaGetSymbolAddress((void**)&xh,  g_xh);
    cudaGetSymbolAddress((void**)&ah,  g_ah);
    cudaGetSymbolAddress((void**)&wqh, g_wqh);
    cudaGetSymbolAddress((void**)&wph, g_wph);
    cudaGetSymbolAddress((void**)&bmb, g_bm);
    cudaGetSymbolAddress((void**)&biasb, g_bias12);

    cudaFuncSetAttribute(gemm_mma_kernel<__half>,
                         cudaFuncAttributeMaxDynamicSharedMemorySize, SMEM_TOT);
    cudaFuncSetAttribute(gemm_mma_kernel<float>,
                         cudaFuncAttributeMaxDynamicSharedMemorySize, SMEM_TOT);

    // conversions + two-stage bias/mask precompute
    {
        int n4 = (M_TOTAL * DIM) / 4;
        f2h_kernel<<<(n4 + 255) / 256, 256>>>((const float4*)x, (uint2*)xh, n4);
        int w4 = (QKV_N * DIM) / 4;
        f2h_kernel<<<(w4 + 255) / 256, 256>>>((const float4*)qkv_w, (uint2*)wqh, w4);
        int p4 = (DIM * DIM) / 4;
        f2h_kernel<<<(p4 + 255) / 256, 256>>>((const float4*)proj_w, (uint2*)wph, p4);
        bias12_prep_kernel<<<(NHEADS * BM_STR + 255) / 256, 256>>>(rpb, rel_i, biasb);
        bm_stream_kernel<<<NMASK * NHEADS, 256>>>(biasb, mask, bmb);
    }

    // 1) QKV projection -> fp16 qkv
    {
        dim3 grid(QKV_N / 128, M_TOTAL / 128);
        gemm_mma_kernel<__half><<<grid, 256, SMEM_TOT>>>(xh, wqh, qkv_b, qkvh, QKV_N);
    }

    // 2) Windowed attention: paired windows sharing the bm row
    win_attn_kernel<<<(NWIN / 2) * NHEADS, 256>>>(qkvh, bmb, ah);

    // 3) Output projection -> fp32 d_out
    {
        dim3 grid(DIM / 128, M_TOTAL / 128);
        gemm_mma_kernel<float><<<grid, 256, SMEM_TOT>>>(ah, wph, proj_b, out, DIM);
    }
}

// round 16
// speedup vs baseline: 1.1512x; 1.1512x over previous
#include <cuda_runtime.h>
#include <cuda_fp16.h>
#include <cstdint>
#include <math.h>

// ---------------------------------------------------------------------------
// Problem constants
// ---------------------------------------------------------------------------
#define NTOK      49
#define DIM       384
#define NHEADS    12
#define HD        32
#define NWIN      4096
#define NMASK     1024
#define M_TOTAL   (NWIN * NTOK)     // 200704
#define QKV_N     (3 * DIM)         // 1152
#define KTOT      384
#define ATTN_SCALE 0.17677669529663687f
#define BM_STR    2404              // padded bias+mask row (floats, 16B-aligned)

// Scratch (__device__ globals; allocation-free rule)
__device__ __align__(128) __half g_qkvh[(size_t)M_TOTAL * QKV_N];
__device__ __align__(128) __half g_xh [(size_t)M_TOTAL * DIM];
__device__ __align__(128) __half g_ah [(size_t)M_TOTAL * DIM];
__device__ __align__(128) __half g_wqh[QKV_N * DIM];
__device__ __align__(128) __half g_wph[DIM * DIM];
__device__ __align__(128) float  g_bias12[NHEADS * BM_STR];              // gathered rpb
__device__ __align__(128) float  g_bm[(size_t)NMASK * NHEADS * BM_STR];  // bias+mask fused

// ---------------------------------------------------------------------------
// Helpers
// ---------------------------------------------------------------------------
__device__ __forceinline__ uint32_t smem_u32(const void* p) {
    uint32_t a;
    asm("{ .reg .u64 t; cvta.to.shared.u64 t, %1; cvt.u32.u64 %0, t; }" : "=r"(a) : "l"(p));
    return a;
}

__device__ __forceinline__ void cpa16(uint32_t dst, const void* src) {
    asm volatile("cp.async.cg.shared.global [%0], [%1], 16;" :: "r"(dst), "l"(src) : "memory");
}
#define CP_COMMIT() asm volatile("cp.async.commit_group;" ::: "memory")
#define CP_WAIT1()  asm volatile("cp.async.wait_group 1;" ::: "memory")
#define CP_WAIT0()  asm volatile("cp.async.wait_group 0;" ::: "memory")

__device__ __forceinline__ void mma_f16(float* d, const uint32_t* a, const uint32_t* b) {
    asm volatile(
        "mma.sync.aligned.m16n8k16.row.col.f32.f16.f16.f32 "
        "{%0,%1,%2,%3}, {%4,%5,%6,%7}, {%8,%9}, {%0,%1,%2,%3};"
        : "+f"(d[0]), "+f"(d[1]), "+f"(d[2]), "+f"(d[3])
        : "r"(a[0]), "r"(a[1]), "r"(a[2]), "r"(a[3]), "r"(b[0]), "r"(b[1]));
}

__device__ __forceinline__ void ldsm_x4(uint32_t* r, uint32_t addr) {
    asm volatile("ldmatrix.sync.aligned.m8n8.x4.shared.b16 {%0,%1,%2,%3}, [%4];"
                 : "=r"(r[0]), "=r"(r[1]), "=r"(r[2]), "=r"(r[3]) : "r"(addr));
}
__device__ __forceinline__ void ldsm_x4_t(uint32_t* r, uint32_t addr) {
    asm volatile("ldmatrix.sync.aligned.m8n8.x4.trans.shared.b16 {%0,%1,%2,%3}, [%4];"
                 : "=r"(r[0]), "=r"(r[1]), "=r"(r[2]), "=r"(r[3]) : "r"(addr));
}

// ---------------------------------------------------------------------------
// fp16 tensor-core GEMM (exact round-12 proven version: BK=32, 3 stages)
// ---------------------------------------------------------------------------
#define BKH      32
#define NSTAGE   3
#define KITERS   (KTOT / BKH)
#define SROWW    20
#define STAGEW   (128 * SROWW)
#define SMEM_TOT (NSTAGE * STAGEW * 2 * 4)

template <typename OutT>
__global__ __launch_bounds__(256, 2)
void gemm_mma_kernel(const __half* __restrict__ A,
                     const __half* __restrict__ W,
                     const float* __restrict__ bias,
                     OutT* __restrict__ C,
                     int Ntot) {
    extern __shared__ __align__(16) uint32_t sm[];
    uint32_t* Asm = sm;
    uint32_t* Bsm = sm + NSTAGE * STAGEW;

    const int tid  = threadIdx.x;
    const int warp = tid >> 5;
    const int lane = tid & 31;
    const int gid  = lane >> 2;
    const int tig  = lane & 3;
    const int wm   = warp & 1;
    const int wn   = warp >> 1;
    const int mb   = blockIdx.y * 128;
    const int nb   = blockIdx.x * 128;

    const int aLane = ((lane & 7) + 8 * ((lane >> 3) & 1)) * SROWW + 4 * (lane >> 4);
    const int bLane = ((lane & 7) + 8 * (lane >> 4)) * SROWW + 4 * ((lane >> 3) & 1);

    auto load_stage = [&](int s, int kt) {
        uint32_t* as = Asm + s * STAGEW;
        uint32_t* bs = Bsm + s * STAGEW;
        const int k0 = kt * BKH;
        #pragma unroll
        for (int i = 0; i < 2; i++) {
            const int f = tid + i * 256;
            const int m = f >> 2;
            const int g = f & 3;
            cpa16(smem_u32(as + m * SROWW + g * 4), A + (size_t)(mb + m) * KTOT + k0 + g * 8);
            cpa16(smem_u32(bs + m * SROWW + g * 4), W + (size_t)(nb + m) * KTOT + k0 + g * 8);
        }
    };

    float acc[4][4][4];
    #pragma unroll
    for (int mt = 0; mt < 4; mt++)
        #pragma unroll
        for (int nt = 0; nt < 4; nt++)
            #pragma unroll
            for (int r = 0; r < 4; r++) acc[mt][nt][r] = 0.0f;

    load_stage(0, 0); CP_COMMIT();
    load_stage(1, 1); CP_COMMIT();

    for (int kt = 0; kt < KITERS; ++kt) {
        CP_WAIT1();
        __syncthreads();

        const int s = kt % NSTAGE;
        if (kt + 2 < KITERS) load_stage((kt + 2) % NSTAGE, kt + 2);
        CP_COMMIT();

        const uint32_t aS = smem_u32(Asm + s * STAGEW);
        const uint32_t bS = smem_u32(Bsm + s * STAGEW);

        #pragma unroll
        for (int ks = 0; ks < 2; ks++) {
            const int kw = ks * 8;
            uint32_t af[4][4], bf[4][2];
            #pragma unroll
            for (int mt = 0; mt < 4; mt++) {
                const int base = (wm * 64 + mt * 16) * SROWW + kw + aLane;
                ldsm_x4(af[mt], aS + base * 4);
            }
            #pragma unroll
            for (int np = 0; np < 2; np++) {
                uint32_t q[4];
                const int base = (wn * 32 + np * 16) * SROWW + kw + bLane;
                ldsm_x4(q, bS + base * 4);
                bf[2 * np + 0][0] = q[0]; bf[2 * np + 0][1] = q[1];
                bf[2 * np + 1][0] = q[2]; bf[2 * np + 1][1] = q[3];
            }
            #pragma unroll
            for (int mt = 0; mt < 4; mt++)
                #pragma unroll
                for (int nt = 0; nt < 4; nt++)
                    mma_f16(acc[mt][nt], af[mt], bf[nt]);
        }
    }

    #pragma unroll
    for (int mt = 0; mt < 4; mt++) {
        const int row = mb + wm * 64 + mt * 16 + gid;
        #pragma unroll
        for (int nt = 0; nt < 4; nt++) {
            const int col = nb + wn * 32 + nt * 8 + 2 * tig;
            const float b0 = bias[col], b1 = bias[col + 1];
            if constexpr (sizeof(OutT) == 4) {
                float2 v0 = make_float2(acc[mt][nt][0] + b0, acc[mt][nt][1] + b1);
                float2 v1 = make_float2(acc[mt][nt][2] + b0, acc[mt][nt][3] + b1);
                *reinterpret_cast<float2*>((float*)C + (size_t)row * Ntot + col)       = v0;
                *reinterpret_cast<float2*>((float*)C + (size_t)(row + 8) * Ntot + col) = v1;
            } else {
                __half2 h0 = __floats2half2_rn(acc[mt][nt][0] + b0, acc[mt][nt][1] + b1);
                __half2 h1 = __floats2half2_rn(acc[mt][nt][2] + b0, acc[mt][nt][3] + b1);
                *reinterpret_cast<__half2*>((__half*)C + (size_t)row * Ntot + col)       = h0;
                *reinterpret_cast<__half2*>((__half*)C + (size_t)(row + 8) * Ntot + col) = h1;
            }
        }
    }
}

// ---------------------------------------------------------------------------
// Prep kernels (proven round-12 versions)
// ---------------------------------------------------------------------------
__global__ void f2h_kernel(const float4* __restrict__ in,
                           uint2* __restrict__ out, int n4) {
    int i = blockIdx.x * blockDim.x + threadIdx.x;
    if (i < n4) {
        float4 v = in[i];
        __half2 h0 = __floats2half2_rn(v.x, v.y);
        __half2 h1 = __floats2half2_rn(v.z, v.w);
        uint2 u;
        u.x = *reinterpret_cast<uint32_t*>(&h0);
        u.y = *reinterpret_cast<uint32_t*>(&h1);
        out[i] = u;
    }
}

__global__ void bias12_prep_kernel(const float* __restrict__ rpb,
                                   const int* __restrict__ rel_idx,
                                   float* __restrict__ out) {
    int i = blockIdx.x * blockDim.x + threadIdx.x;
    if (i < NHEADS * BM_STR) {
        const int h = i / BM_STR;
        const int e = i - h * BM_STR;
        out[i] = (e < NTOK * NTOK) ? rpb[rel_idx[e] * NHEADS + h] : 0.0f;
    }
}

__global__ void bm_stream_kernel(const float* __restrict__ bias12,
                                 const float* __restrict__ mask,
                                 float* __restrict__ out) {
    const int row = blockIdx.x;
    const int m = row / NHEADS;
    const int h = row - m * NHEADS;
    const float* mrow = mask + (size_t)m * (NTOK * NTOK);
    const float4* brow = reinterpret_cast<const float4*>(bias12 + h * BM_STR);
    float4* orow = reinterpret_cast<float4*>(out + (size_t)row * BM_STR);
    for (int g = threadIdx.x; g < BM_STR / 4; g += 256) {
        const int e0 = g * 4;
        float4 b = brow[g];
        float4 v;
        v.x = (e0 + 0 < NTOK * NTOK) ? b.x + mrow[e0 + 0] : 0.0f;
        v.y = (e0 + 1 < NTOK * NTOK) ? b.y + mrow[e0 + 1] : 0.0f;
        v.z = (e0 + 2 < NTOK * NTOK) ? b.z + mrow[e0 + 2] : 0.0f;
        v.w = (e0 + 3 < NTOK * NTOK) ? b.w + mrow[e0 + 3] : 0.0f;
        orow[g] = v;
    }
}

// ---------------------------------------------------------------------------
// Window attention v6: r12 envelope (128 thr, 1 window, 6 CTAs/SM) with
// register-resident softmax (quad shuffles), no Sf array, 2 barriers.
// ---------------------------------------------------------------------------
__global__ __launch_bounds__(128, 6)
void win_attn_kernel(const __half* __restrict__ qkv,
                     const float* __restrict__ bm,
                     __half* __restrict__ attout) {
    const int w = blockIdx.x / NHEADS;
    const int h = blockIdx.x % NHEADS;
    const int tid  = threadIdx.x;
    const int warp = tid >> 5;
    const int lane = tid & 31;
    const int gid  = lane >> 2;
    const int tig  = lane & 3;

    // Q (5120) + K (5120); Ph[64][72] (9216 B) aliases this region after scores.
    __shared__ __align__(16) char  ub[64 * 40 * 2 * 2];
    __shared__ __align__(16) __half Vh[64][40];
    __shared__ __align__(16) float  BMs[BM_STR];

    __half (*Qh)[40] = reinterpret_cast<__half(*)[40]>(ub);
    __half (*Kh)[40] = reinterpret_cast<__half(*)[40]>(ub + 64 * 40 * 2);
    __half (*Ph)[72] = reinterpret_cast<__half(*)[72]>(ub);

    // ---- Prefetch: qkv rows (588 x 16B) + bm row (601 x 16B) ----
    const __half* base = qkv + (size_t)w * NTOK * QKV_N + h * HD;
    for (int idx = tid; idx < 3 * NTOK * 4; idx += 128) {
        const int m = idx / (NTOK * 4);
        const int rem = idx - m * (NTOK * 4);
        const int i = rem >> 2;
        const int g = rem & 3;
        __half* dst = (m == 0) ? &Qh[i][0] : (m == 1) ? &Kh[i][0] : &Vh[i][0];
        cpa16(smem_u32(dst + g * 8), base + (size_t)i * QKV_N + m * DIM + g * 8);
    }
    {
        const float* bmrow = bm + (size_t)((w & (NMASK - 1)) * NHEADS + h) * BM_STR;
        for (int idx = tid; idx < BM_STR / 4; idx += 128)
            cpa16(smem_u32(&BMs[idx * 4]), bmrow + idx * 4);
    }
    CP_COMMIT();

    // ---- Zero V pad rows 49..63 only (P pads are exact zeros from softmax;
    // Q/K pad garbage only affects discarded rows / overridden columns) ----
    const uint4 z4 = make_uint4(0, 0, 0, 0);
    for (int idx = tid; idx < 75; idx += 128) {
        const int r = 49 + idx / 5;
        const int g = idx % 5;
        reinterpret_cast<uint4*>(&Vh[r][0])[g] = z4;
    }
    CP_WAIT0();
    __syncthreads();

    // ---- Scores: S = Q K^T ----
    const uint32_t QS = smem_u32(&Qh[0][0]);
    const uint32_t KS = smem_u32(&Kh[0][0]);
    const int aL = ((lane & 7) + 8 * ((lane >> 3) & 1)) * 20 + 4 * (lane >> 4);
    const int bL = ((lane & 7) + 8 * (lane >> 4)) * 20 + 4 * ((lane >> 3) & 1);

    float acc[8][4];
    #pragma unroll
    for (int a = 0; a < 8; a++)
        #pragma unroll
        for (int r = 0; r < 4; r++) acc[a][r] = 0.0f;

    #pragma unroll
    for (int ks = 0; ks < 2; ks++) {
        uint32_t af[4];
        ldsm_x4(af, QS + (uint32_t)(warp * 16 * 20 + ks * 8 + aL) * 4);
        #pragma unroll
        for (int nb = 0; nb < 4; nb++) {
            uint32_t q[4];
            ldsm_x4(q, KS + (uint32_t)(nb * 16 * 20 + ks * 8 + bL) * 4);
            mma_f16(acc[nb * 2 + 0], af, q + 0);
            mma_f16(acc[nb * 2 + 1], af, q + 2);
        }
    }

    // ---- Register softmax: row r lives in this quad (j = nt*8+2tig+c) ----
    // acc[nt][rr*2+c] -> scaled+biased score -> exp -> P (normalized)
    #pragma unroll
    for (int rr = 0; rr < 2; rr++) {
        const int i = warp * 16 + gid + rr * 8;
        const bool vi = (i < NTOK);
        const int ib = i * NTOK;
        float mx = -1e30f;
        #pragma unroll
        for (int nt = 0; nt < 8; nt++) {
            const int j = nt * 8 + 2 * tig;
            float v0 = (vi && j     < NTOK) ? fmaf(acc[nt][rr * 2 + 0], ATTN_SCALE, BMs[ib + j])     : -1e30f;
            float v1 = (vi && j + 1 < NTOK) ? fmaf(acc[nt][rr * 2 + 1], ATTN_SCALE, BMs[ib + j + 1]) : -1e30f;
            acc[nt][rr * 2 + 0] = v0;
            acc[nt][rr * 2 + 1] = v1;
            mx = fmaxf(mx, fmaxf(v0, v1));
        }
        mx = fmaxf(mx, __shfl_xor_sync(0xffffffffu, mx, 1));
        mx = fmaxf(mx, __shfl_xor_sync(0xffffffffu, mx, 2));
        float s = 0.0f;
        #pragma unroll
        for (int nt = 0; nt < 8; nt++) {
            const float e0 = __expf(acc[nt][rr * 2 + 0] - mx);
            const float e1 = __expf(acc[nt][rr * 2 + 1] - mx);
            acc[nt][rr * 2 + 0] = e0;
            acc[nt][rr * 2 + 1] = e1;
            s += e0 + e1;
        }
        s += __shfl_xor_sync(0xffffffffu, s, 1);
        s += __shfl_xor_sync(0xffffffffu, s, 2);
        const float inv = 1.0f / s;
        #pragma unroll
        for (int nt = 0; nt < 8; nt++) {
            acc[nt][rr * 2 + 0] *= inv;
            acc[nt][rr * 2 + 1] *= inv;
        }
    }

    __syncthreads();   // all Q/K ldmatrix complete -> Ph region reusable

    // ---- Store P (fp16, half2), covers ALL of Ph[0..63][0..63] ----
    #pragma unroll
    for (int rr = 0; rr < 2; rr++) {
        const int r = warp * 16 + gid + rr * 8;
        #pragma unroll
        for (int nt = 0; nt < 8; nt++) {
            __half2 p = __floats2half2_rn(acc[nt][rr * 2 + 0], acc[nt][rr * 2 + 1]);
            *reinterpret_cast<__half2*>(&Ph[r][nt * 8 + 2 * tig]) = p;
        }
    }
    __syncwarp();      // PV reads only this warp's own P rows

    // ---- PV: O = P V ----
    const uint32_t PS = smem_u32(&Ph[0][0]);
    const uint32_t VS = smem_u32(&Vh[0][0]);
    const int aLp = ((lane & 7) + 8 * ((lane >> 3) & 1)) * 36 + 4 * (lane >> 4);
    const int vL  = ((lane & 7) + 8 * ((lane >> 3) & 1)) * 20 + 4 * (lane >> 4);

    float pacc[4][4];
    #pragma unroll
    for (int a = 0; a < 4; a++)
        #pragma unroll
        for (int r = 0; r < 4; r++) pacc[a][r] = 0.0f;

    #pragma unroll
    for (int ks = 0; ks < 4; ks++) {
        uint32_t pf[4];
        ldsm_x4(pf, PS + (uint32_t)(warp * 16 * 36 + ks * 8 + aLp) * 4);
        uint32_t v0[4], v1[4];
        ldsm_x4_t(v0, VS + (uint32_t)(ks * 16 * 20 + vL) * 4);
        ldsm_x4_t(v1, VS + (uint32_t)(ks * 16 * 20 + 8 + vL) * 4);
        mma_f16(pacc[0], pf, v0 + 0);
        mma_f16(pacc[1], pf, v0 + 2);
        mma_f16(pacc[2], pf, v1 + 0);
        mma_f16(pacc[3], pf, v1 + 2);
    }

    // ---- Store O (fp16) ----
    {
        __half* ob = attout + (size_t)w * NTOK * DIM + h * HD;
        const int i0 = warp * 16 + gid;
        #pragma unroll
        for (int nt = 0; nt < 4; nt++) {
            const int d = nt * 8 + 2 * tig;
            #pragma unroll
            for (int rr = 0; rr < 2; rr++) {
                const int i = i0 + rr * 8;
                if (i < NTOK) {
                    __half2 hv = __floats2half2_rn(pacc[nt][rr * 2], pacc[nt][rr * 2 + 1]);
                    *reinterpret_cast<__half2*>(ob + (size_t)i * DIM + d) = hv;
                }
            }
        }
    }
}

// ---------------------------------------------------------------------------
// Launch
// ---------------------------------------------------------------------------
extern "C" void kernel_launch(void* const* d_in, const int* in_sizes, int n_in,
                              void* d_out, int out_size) {
    const float* x      = (const float*)d_in[0];
    const float* mask   = (const float*)d_in[1];
    const float* rpb    = (const float*)d_in[2];
    const float* qkv_w  = (const float*)d_in[3];
    const float* qkv_b  = (const float*)d_in[4];
    const float* proj_w = (const float*)d_in[5];
    const float* proj_b = (const float*)d_in[6];
    const int*   rel_i  = (const int*)d_in[7];
    float* out = (float*)d_out;

    __half *qkvh, *xh, *ah, *wqh, *wph;
    float *bmb, *biasb;
    cudaGetSymbolAddress((void**)&qkvh, g_qkvh);
    cudaGetSymbolAddress((void**)&xh,  g_xh);
    cudaGetSymbolAddress((void**)&ah,  g_ah);
    cudaGetSymbolAddress((void**)&wqh, g_wqh);
    cudaGetSymbolAddress((void**)&wph, g_wph);
    cudaGetSymbolAddress((void**)&bmb, g_bm);
    cudaGetSymbolAddress((void**)&biasb, g_bias12);

    cudaFuncSetAttribute(gemm_mma_kernel<__half>,
                         cudaFuncAttributeMaxDynamicSharedMemorySize, SMEM_TOT);
    cudaFuncSetAttribute(gemm_mma_kernel<float>,
                         cudaFuncAttributeMaxDynamicSharedMemorySize, SMEM_TOT);

    // conversions + two-stage bias/mask precompute
    {
        int n4 = (M_TOTAL * DIM) / 4;
        f2h_kernel<<<(n4 + 255) / 256, 256>>>((const float4*)x, (uint2*)xh, n4);
        int w4 = (QKV_N * DIM) / 4;
        f2h_kernel<<<(w4 + 255) / 256, 256>>>((const float4*)qkv_w, (uint2*)wqh, w4);
        int p4 = (DIM * DIM) / 4;
        f2h_kernel<<<(p4 + 255) / 256, 256>>>((const float4*)proj_w, (uint2*)wph, p4);
        bias12_prep_kernel<<<(NHEADS * BM_STR + 255) / 256, 256>>>(rpb, rel_i, biasb);
        bm_stream_kernel<<<NMASK * NHEADS, 256>>>(biasb, mask, bmb);
    }

    // 1) QKV projection -> fp16 qkv
    {
        dim3 grid(QKV_N / 128, M_TOTAL / 128);
        gemm_mma_kernel<__half><<<grid, 256, SMEM_TOT>>>(xh, wqh, qkv_b, qkvh, QKV_N);
    }

    // 2) Windowed attention (register-softmax v6)
    win_attn_kernel<<<NWIN * NHEADS, 128>>>(qkvh, bmb, ah);

    // 3) Output projection -> fp32 d_out
    {
        dim3 grid(DIM / 128, M_TOTAL / 128);
        gemm_mma_kernel<float><<<grid, 256, SMEM_TOT>>>(ah, wph, proj_b, out, DIM);
    }
}

// round 17
// speedup vs baseline: 1.1745x; 1.0203x over previous
#include <cuda_runtime.h>
#include <cuda_fp16.h>
#include <cstdint>
#include <math.h>

// ---------------------------------------------------------------------------
// Problem constants
// ---------------------------------------------------------------------------
#define NTOK      49
#define DIM       384
#define NHEADS    12
#define HD        32
#define NWIN      4096
#define NMASK     1024
#define M_TOTAL   (NWIN * NTOK)     // 200704
#define QKV_N     (3 * DIM)         // 1152
#define KTOT      384
#define ATTN_SCALE 0.17677669529663687f
#define BM_STR    2404              // padded fp32 row (bias12 table)
#define BMH_STR   2408              // padded fp16 row (fused bm table, 16B mult)

// Scratch (__device__ globals; allocation-free rule)
__device__ __align__(128) __half g_qkvh[(size_t)M_TOTAL * QKV_N];
__device__ __align__(128) __half g_xh [(size_t)M_TOTAL * DIM];
__device__ __align__(128) __half g_ah [(size_t)M_TOTAL * DIM];
__device__ __align__(128) __half g_wqh[QKV_N * DIM];
__device__ __align__(128) __half g_wph[DIM * DIM];
__device__ __align__(128) float  g_bias12[NHEADS * BM_STR];                 // gathered rpb
__device__ __align__(128) __half g_bmh[(size_t)NMASK * NHEADS * BMH_STR];   // bias+mask fp16

// ---------------------------------------------------------------------------
// Helpers
// ---------------------------------------------------------------------------
__device__ __forceinline__ uint32_t smem_u32(const void* p) {
    uint32_t a;
    asm("{ .reg .u64 t; cvta.to.shared.u64 t, %1; cvt.u32.u64 %0, t; }" : "=r"(a) : "l"(p));
    return a;
}

__device__ __forceinline__ void cpa16(uint32_t dst, const void* src) {
    asm volatile("cp.async.cg.shared.global [%0], [%1], 16;" :: "r"(dst), "l"(src) : "memory");
}
#define CP_COMMIT() asm volatile("cp.async.commit_group;" ::: "memory")
#define CP_WAIT1()  asm volatile("cp.async.wait_group 1;" ::: "memory")
#define CP_WAIT0()  asm volatile("cp.async.wait_group 0;" ::: "memory")

__device__ __forceinline__ void mma_f16(float* d, const uint32_t* a, const uint32_t* b) {
    asm volatile(
        "mma.sync.aligned.m16n8k16.row.col.f32.f16.f16.f32 "
        "{%0,%1,%2,%3}, {%4,%5,%6,%7}, {%8,%9}, {%0,%1,%2,%3};"
        : "+f"(d[0]), "+f"(d[1]), "+f"(d[2]), "+f"(d[3])
        : "r"(a[0]), "r"(a[1]), "r"(a[2]), "r"(a[3]), "r"(b[0]), "r"(b[1]));
}

__device__ __forceinline__ void ldsm_x4(uint32_t* r, uint32_t addr) {
    asm volatile("ldmatrix.sync.aligned.m8n8.x4.shared.b16 {%0,%1,%2,%3}, [%4];"
                 : "=r"(r[0]), "=r"(r[1]), "=r"(r[2]), "=r"(r[3]) : "r"(addr));
}
__device__ __forceinline__ void ldsm_x4_t(uint32_t* r, uint32_t addr) {
    asm volatile("ldmatrix.sync.aligned.m8n8.x4.trans.shared.b16 {%0,%1,%2,%3}, [%4];"
                 : "=r"(r[0]), "=r"(r[1]), "=r"(r[2]), "=r"(r[3]) : "r"(addr));
}

// ---------------------------------------------------------------------------
// fp16 tensor-core GEMM (exact round-12 proven version: BK=32, 3 stages)
// ---------------------------------------------------------------------------
#define BKH      32
#define NSTAGE   3
#define KITERS   (KTOT / BKH)
#define SROWW    20
#define STAGEW   (128 * SROWW)
#define SMEM_TOT (NSTAGE * STAGEW * 2 * 4)

template <typename OutT>
__global__ __launch_bounds__(256, 2)
void gemm_mma_kernel(const __half* __restrict__ A,
                     const __half* __restrict__ W,
                     const float* __restrict__ bias,
                     OutT* __restrict__ C,
                     int Ntot) {
    extern __shared__ __align__(16) uint32_t sm[];
    uint32_t* Asm = sm;
    uint32_t* Bsm = sm + NSTAGE * STAGEW;

    const int tid  = threadIdx.x;
    const int warp = tid >> 5;
    const int lane = tid & 31;
    const int gid  = lane >> 2;
    const int tig  = lane & 3;
    const int wm   = warp & 1;
    const int wn   = warp >> 1;
    const int mb   = blockIdx.y * 128;
    const int nb   = blockIdx.x * 128;

    const int aLane = ((lane & 7) + 8 * ((lane >> 3) & 1)) * SROWW + 4 * (lane >> 4);
    const int bLane = ((lane & 7) + 8 * (lane >> 4)) * SROWW + 4 * ((lane >> 3) & 1);

    auto load_stage = [&](int s, int kt) {
        uint32_t* as = Asm + s * STAGEW;
        uint32_t* bs = Bsm + s * STAGEW;
        const int k0 = kt * BKH;
        #pragma unroll
        for (int i = 0; i < 2; i++) {
            const int f = tid + i * 256;
            const int m = f >> 2;
            const int g = f & 3;
            cpa16(smem_u32(as + m * SROWW + g * 4), A + (size_t)(mb + m) * KTOT + k0 + g * 8);
            cpa16(smem_u32(bs + m * SROWW + g * 4), W + (size_t)(nb + m) * KTOT + k0 + g * 8);
        }
    };

    float acc[4][4][4];
    #pragma unroll
    for (int mt = 0; mt < 4; mt++)
        #pragma unroll
        for (int nt = 0; nt < 4; nt++)
            #pragma unroll
            for (int r = 0; r < 4; r++) acc[mt][nt][r] = 0.0f;

    load_stage(0, 0); CP_COMMIT();
    load_stage(1, 1); CP_COMMIT();

    for (int kt = 0; kt < KITERS; ++kt) {
        CP_WAIT1();
        __syncthreads();

        const int s = kt % NSTAGE;
        if (kt + 2 < KITERS) load_stage((kt + 2) % NSTAGE, kt + 2);
        CP_COMMIT();

        const uint32_t aS = smem_u32(Asm + s * STAGEW);
        const uint32_t bS = smem_u32(Bsm + s * STAGEW);

        #pragma unroll
        for (int ks = 0; ks < 2; ks++) {
            const int kw = ks * 8;
            uint32_t af[4][4], bf[4][2];
            #pragma unroll
            for (int mt = 0; mt < 4; mt++) {
                const int base = (wm * 64 + mt * 16) * SROWW + kw + aLane;
                ldsm_x4(af[mt], aS + base * 4);
            }
            #pragma unroll
            for (int np = 0; np < 2; np++) {
                uint32_t q[4];
                const int base = (wn * 32 + np * 16) * SROWW + kw + bLane;
                ldsm_x4(q, bS + base * 4);
                bf[2 * np + 0][0] = q[0]; bf[2 * np + 0][1] = q[1];
                bf[2 * np + 1][0] = q[2]; bf[2 * np + 1][1] = q[3];
            }
            #pragma unroll
            for (int mt = 0; mt < 4; mt++)
                #pragma unroll
                for (int nt = 0; nt < 4; nt++)
                    mma_f16(acc[mt][nt], af[mt], bf[nt]);
        }
    }

    #pragma unroll
    for (int mt = 0; mt < 4; mt++) {
        const int row = mb + wm * 64 + mt * 16 + gid;
        #pragma unroll
        for (int nt = 0; nt < 4; nt++) {
            const int col = nb + wn * 32 + nt * 8 + 2 * tig;
            const float b0 = bias[col], b1 = bias[col + 1];
            if constexpr (sizeof(OutT) == 4) {
                float2 v0 = make_float2(acc[mt][nt][0] + b0, acc[mt][nt][1] + b1);
                float2 v1 = make_float2(acc[mt][nt][2] + b0, acc[mt][nt][3] + b1);
                *reinterpret_cast<float2*>((float*)C + (size_t)row * Ntot + col)       = v0;
                *reinterpret_cast<float2*>((float*)C + (size_t)(row + 8) * Ntot + col) = v1;
            } else {
                __half2 h0 = __floats2half2_rn(acc[mt][nt][0] + b0, acc[mt][nt][1] + b1);
                __half2 h1 = __floats2half2_rn(acc[mt][nt][2] + b0, acc[mt][nt][3] + b1);
                *reinterpret_cast<__half2*>((__half*)C + (size_t)row * Ntot + col)       = h0;
                *reinterpret_cast<__half2*>((__half*)C + (size_t)(row + 8) * Ntot + col) = h1;
            }
        }
    }
}

// ---------------------------------------------------------------------------
// Prep kernels
// ---------------------------------------------------------------------------
__global__ void f2h_kernel(const float4* __restrict__ in,
                           uint2* __restrict__ out, int n4) {
    int i = blockIdx.x * blockDim.x + threadIdx.x;
    if (i < n4) {
        float4 v = in[i];
        __half2 h0 = __floats2half2_rn(v.x, v.y);
        __half2 h1 = __floats2half2_rn(v.z, v.w);
        uint2 u;
        u.x = *reinterpret_cast<uint32_t*>(&h0);
        u.y = *reinterpret_cast<uint32_t*>(&h1);
        out[i] = u;
    }
}

__global__ void bias12_prep_kernel(const float* __restrict__ rpb,
                                   const int* __restrict__ rel_idx,
                                   float* __restrict__ out) {
    int i = blockIdx.x * blockDim.x + threadIdx.x;
    if (i < NHEADS * BM_STR) {
        const int h = i / BM_STR;
        const int e = i - h * BM_STR;
        out[i] = (e < NTOK * NTOK) ? rpb[rel_idx[e] * NHEADS + h] : 0.0f;
    }
}

// bmh[(m*12+h)][e] = half(bias12[h][e] + mask[m][e])  — streaming, fp16 output
__global__ void bm_stream_kernel(const float* __restrict__ bias12,
                                 const float* __restrict__ mask,
                                 __half* __restrict__ out) {
    const int row = blockIdx.x;
    const int m = row / NHEADS;
    const int h = row - m * NHEADS;
    const float* mrow = mask + (size_t)m * (NTOK * NTOK);
    const float* brow = bias12 + h * BM_STR;
    __half2* orow = reinterpret_cast<__half2*>(out + (size_t)row * BMH_STR);
    for (int g = threadIdx.x; g < BMH_STR / 2; g += 256) {
        const int e0 = g * 2;
        float v0 = (e0     < NTOK * NTOK) ? brow[e0]     + mrow[e0]     : 0.0f;
        float v1 = (e0 + 1 < NTOK * NTOK) ? brow[e0 + 1] + mrow[e0 + 1] : 0.0f;
        orow[g] = __floats2half2_rn(v0, v1);
    }
}

// ---------------------------------------------------------------------------
// Window attention v7: r16 register-softmax kernel; bm table read as fp16.
// ---------------------------------------------------------------------------
__global__ __launch_bounds__(128, 6)
void win_attn_kernel(const __half* __restrict__ qkv,
                     const __half* __restrict__ bmh,
                     __half* __restrict__ attout) {
    const int w = blockIdx.x / NHEADS;
    const int h = blockIdx.x % NHEADS;
    const int tid  = threadIdx.x;
    const int warp = tid >> 5;
    const int lane = tid & 31;
    const int gid  = lane >> 2;
    const int tig  = lane & 3;

    // Q (5120) + K (5120); Ph[64][72] (9216 B) aliases this region after scores.
    __shared__ __align__(16) char  ub[64 * 40 * 2 * 2];
    __shared__ __align__(16) __half Vh[64][40];
    __shared__ __align__(16) __half BMs[BMH_STR];

    __half (*Qh)[40] = reinterpret_cast<__half(*)[40]>(ub);
    __half (*Kh)[40] = reinterpret_cast<__half(*)[40]>(ub + 64 * 40 * 2);
    __half (*Ph)[72] = reinterpret_cast<__half(*)[72]>(ub);

    // ---- Prefetch: qkv rows (588 x 16B) + bm row (301 x 16B) ----
    const __half* base = qkv + (size_t)w * NTOK * QKV_N + h * HD;
    for (int idx = tid; idx < 3 * NTOK * 4; idx += 128) {
        const int m = idx / (NTOK * 4);
        const int rem = idx - m * (NTOK * 4);
        const int i = rem >> 2;
        const int g = rem & 3;
        __half* dst = (m == 0) ? &Qh[i][0] : (m == 1) ? &Kh[i][0] : &Vh[i][0];
        cpa16(smem_u32(dst + g * 8), base + (size_t)i * QKV_N + m * DIM + g * 8);
    }
    {
        const __half* bmrow = bmh + (size_t)((w & (NMASK - 1)) * NHEADS + h) * BMH_STR;
        for (int idx = tid; idx < BMH_STR / 8; idx += 128)
            cpa16(smem_u32(&BMs[idx * 8]), bmrow + idx * 8);
    }
    CP_COMMIT();

    // ---- Zero V pad rows 49..63 only ----
    const uint4 z4 = make_uint4(0, 0, 0, 0);
    for (int idx = tid; idx < 75; idx += 128) {
        const int r = 49 + idx / 5;
        const int g = idx % 5;
        reinterpret_cast<uint4*>(&Vh[r][0])[g] = z4;
    }
    CP_WAIT0();
    __syncthreads();

    // ---- Scores: S = Q K^T ----
    const uint32_t QS = smem_u32(&Qh[0][0]);
    const uint32_t KS = smem_u32(&Kh[0][0]);
    const int aL = ((lane & 7) + 8 * ((lane >> 3) & 1)) * 20 + 4 * (lane >> 4);
    const int bL = ((lane & 7) + 8 * (lane >> 4)) * 20 + 4 * ((lane >> 3) & 1);

    float acc[8][4];
    #pragma unroll
    for (int a = 0; a < 8; a++)
        #pragma unroll
        for (int r = 0; r < 4; r++) acc[a][r] = 0.0f;

    #pragma unroll
    for (int ks = 0; ks < 2; ks++) {
        uint32_t af[4];
        ldsm_x4(af, QS + (uint32_t)(warp * 16 * 20 + ks * 8 + aL) * 4);
        #pragma unroll
        for (int nb = 0; nb < 4; nb++) {
            uint32_t q[4];
            ldsm_x4(q, KS + (uint32_t)(nb * 16 * 20 + ks * 8 + bL) * 4);
            mma_f16(acc[nb * 2 + 0], af, q + 0);
            mma_f16(acc[nb * 2 + 1], af, q + 2);
        }
    }

    // ---- Register softmax (quad shuffles); bm from fp16 smem ----
    #pragma unroll
    for (int rr = 0; rr < 2; rr++) {
        const int i = warp * 16 + gid + rr * 8;
        const bool vi = (i < NTOK);
        const int ib = i * NTOK;
        float mx = -1e30f;
        #pragma unroll
        for (int nt = 0; nt < 8; nt++) {
            const int j = nt * 8 + 2 * tig;
            float v0 = (vi && j < NTOK)
                       ? fmaf(acc[nt][rr * 2 + 0], ATTN_SCALE, __half2float(BMs[ib + j]))
                       : -1e30f;
            float v1 = (vi && j + 1 < NTOK)
                       ? fmaf(acc[nt][rr * 2 + 1], ATTN_SCALE, __half2float(BMs[ib + j + 1]))
                       : -1e30f;
            acc[nt][rr * 2 + 0] = v0;
            acc[nt][rr * 2 + 1] = v1;
            mx = fmaxf(mx, fmaxf(v0, v1));
        }
        mx = fmaxf(mx, __shfl_xor_sync(0xffffffffu, mx, 1));
        mx = fmaxf(mx, __shfl_xor_sync(0xffffffffu, mx, 2));
        float s = 0.0f;
        #pragma unroll
        for (int nt = 0; nt < 8; nt++) {
            const float e0 = __expf(acc[nt][rr * 2 + 0] - mx);
            const float e1 = __expf(acc[nt][rr * 2 + 1] - mx);
            acc[nt][rr * 2 + 0] = e0;
            acc[nt][rr * 2 + 1] = e1;
            s += e0 + e1;
        }
        s += __shfl_xor_sync(0xffffffffu, s, 1);
        s += __shfl_xor_sync(0xffffffffu, s, 2);
        const float inv = 1.0f / s;
        #pragma unroll
        for (int nt = 0; nt < 8; nt++) {
            acc[nt][rr * 2 + 0] *= inv;
            acc[nt][rr * 2 + 1] *= inv;
        }
    }

    __syncthreads();   // all Q/K ldmatrix complete -> Ph region reusable

    // ---- Store P (fp16, half2), covers ALL of Ph[0..63][0..63] ----
    #pragma unroll
    for (int rr = 0; rr < 2; rr++) {
        const int r = warp * 16 + gid + rr * 8;
        #pragma unroll
        for (int nt = 0; nt < 8; nt++) {
            __half2 p = __floats2half2_rn(acc[nt][rr * 2 + 0], acc[nt][rr * 2 + 1]);
            *reinterpret_cast<__half2*>(&Ph[r][nt * 8 + 2 * tig]) = p;
        }
    }
    __syncwarp();      // PV reads only this warp's own P rows

    // ---- PV: O = P V ----
    const uint32_t PS = smem_u32(&Ph[0][0]);
    const uint32_t VS = smem_u32(&Vh[0][0]);
    const int aLp = ((lane & 7) + 8 * ((lane >> 3) & 1)) * 36 + 4 * (lane >> 4);
    const int vL  = ((lane & 7) + 8 * ((lane >> 3) & 1)) * 20 + 4 * (lane >> 4);

    float pacc[4][4];
    #pragma unroll
    for (int a = 0; a < 4; a++)
        #pragma unroll
        for (int r = 0; r < 4; r++) pacc[a][r] = 0.0f;

    #pragma unroll
    for (int ks = 0; ks < 4; ks++) {
        uint32_t pf[4];
        ldsm_x4(pf, PS + (uint32_t)(warp * 16 * 36 + ks * 8 + aLp) * 4);
        uint32_t v0[4], v1[4];
        ldsm_x4_t(v0, VS + (uint32_t)(ks * 16 * 20 + vL) * 4);
        ldsm_x4_t(v1, VS + (uint32_t)(ks * 16 * 20 + 8 + vL) * 4);
        mma_f16(pacc[0], pf, v0 + 0);
        mma_f16(pacc[1], pf, v0 + 2);
        mma_f16(pacc[2], pf, v1 + 0);
        mma_f16(pacc[3], pf, v1 + 2);
    }

    // ---- Store O (fp16) ----
    {
        __half* ob = attout + (size_t)w * NTOK * DIM + h * HD;
        const int i0 = warp * 16 + gid;
        #pragma unroll
        for (int nt = 0; nt < 4; nt++) {
            const int d = nt * 8 + 2 * tig;
            #pragma unroll
            for (int rr = 0; rr < 2; rr++) {
                const int i = i0 + rr * 8;
                if (i < NTOK) {
                    __half2 hv = __floats2half2_rn(pacc[nt][rr * 2], pacc[nt][rr * 2 + 1]);
                    *reinterpret_cast<__half2*>(ob + (size_t)i * DIM + d) = hv;
                }
            }
        }
    }
}

// ---------------------------------------------------------------------------
// Launch
// ---------------------------------------------------------------------------
extern "C" void kernel_launch(void* const* d_in, const int* in_sizes, int n_in,
                              void* d_out, int out_size) {
    const float* x      = (const float*)d_in[0];
    const float* mask   = (const float*)d_in[1];
    const float* rpb    = (const float*)d_in[2];
    const float* qkv_w  = (const float*)d_in[3];
    const float* qkv_b  = (const float*)d_in[4];
    const float* proj_w = (const float*)d_in[5];
    const float* proj_b = (const float*)d_in[6];
    const int*   rel_i  = (const int*)d_in[7];
    float* out = (float*)d_out;

    __half *qkvh, *xh, *ah, *wqh, *wph, *bmhb;
    float *biasb;
    cudaGetSymbolAddress((void**)&qkvh, g_qkvh);
    cudaGetSymbolAddress((void**)&xh,  g_xh);
    cudaGetSymbolAddress((void**)&ah,  g_ah);
    cudaGetSymbolAddress((void**)&wqh, g_wqh);
    cudaGetSymbolAddress((void**)&wph, g_wph);
    cudaGetSymbolAddress((void**)&bmhb, g_bmh);
    cudaGetSymbolAddress((void**)&biasb, g_bias12);

    cudaFuncSetAttribute(gemm_mma_kernel<__half>,
                         cudaFuncAttributeMaxDynamicSharedMemorySize, SMEM_TOT);
    cudaFuncSetAttribute(gemm_mma_kernel<float>,
                         cudaFuncAttributeMaxDynamicSharedMemorySize, SMEM_TOT);

    // conversions + two-stage bias/mask precompute (fp16 table)
    {
        int n4 = (M_TOTAL * DIM) / 4;
        f2h_kernel<<<(n4 + 255) / 256, 256>>>((const float4*)x, (uint2*)xh, n4);
        int w4 = (QKV_N * DIM) / 4;
        f2h_kernel<<<(w4 + 255) / 256, 256>>>((const float4*)qkv_w, (uint2*)wqh, w4);
        int p4 = (DIM * DIM) / 4;
        f2h_kernel<<<(p4 + 255) / 256, 256>>>((const float4*)proj_w, (uint2*)wph, p4);
        bias12_prep_kernel<<<(NHEADS * BM_STR + 255) / 256, 256>>>(rpb, rel_i, biasb);
        bm_stream_kernel<<<NMASK * NHEADS, 256>>>(biasb, mask, bmhb);
    }

    // 1) QKV projection -> fp16 qkv
    {
        dim3 grid(QKV_N / 128, M_TOTAL / 128);
        gemm_mma_kernel<__half><<<grid, 256, SMEM_TOT>>>(xh, wqh, qkv_b, qkvh, QKV_N);
    }

    // 2) Windowed attention (register softmax, fp16 bm)
    win_attn_kernel<<<NWIN * NHEADS, 128>>>(qkvh, bmhb, ah);

    // 3) Output projection -> fp32 d_out
    {
        dim3 grid(DIM / 128, M_TOTAL / 128);
        gemm_mma_kernel<float><<<grid, 256, SMEM_TOT>>>(ah, wph, proj_b, out, DIM);
    }
}